// round 16
// baseline (speedup 1.0000x reference)
#include <cuda_runtime.h>
#include <cuda_fp16.h>
#include <cstdint>

#define EXPERTS 16
#define FDIM 128
#define HDIM 256
#define ODIM 64
#define BMAX 262144
#define MMAX (BMAX/EXPERTS)
#define EQCAP 8192
#define BM 128
#define NCTA 9
#define NTHR 512

// ---------------- scratch ----------------
struct ZeroBlk {
    unsigned hist[EXPERTS * 65536];
    unsigned hist2[EXPERTS * 65536];
    unsigned selMask[BMAX];
    int      eqCnt[EXPERTS];
    int      idxCnt[EXPERTS];
    int      scnt[2][EXPERTS];
};
__device__ ZeroBlk  g_z;
__device__ unsigned g_csum[2][EXPERTS][8];
__device__ unsigned g_keys[(size_t)EXPERTS * BMAX];
__device__ unsigned g_b16[EXPERTS];
__device__ unsigned g_rankInB[EXPERTS];
__device__ unsigned g_T[EXPERTS];
__device__ unsigned g_needEq[EXPERTS];
__device__ int      g_eqList[EXPERTS * EQCAP];
__device__ int      g_idx[EXPERTS * MMAX];
__device__ __half   g_w1h[(size_t)EXPERTS * HDIM * FDIM];
__device__ __half   g_w2h[(size_t)EXPERTS * ODIM * HDIM];
__device__ __half   g_feat16[(size_t)BMAX * FDIM];

// ---------------- helpers ----------------
__device__ __forceinline__ uint32_t smem_u32(const void* p) {
    uint32_t a;
    asm("{ .reg .u64 t; cvta.to.shared.u64 t, %1; cvt.u32.u64 %0, t; }" : "=r"(a) : "l"(p));
    return a;
}
#define LDSM_X4(r0,r1,r2,r3, addr) \
    asm volatile("ldmatrix.sync.aligned.m8n8.x4.shared.b16 {%0,%1,%2,%3}, [%4];" \
        : "=r"(r0),"=r"(r1),"=r"(r2),"=r"(r3) : "r"(addr))
#define MMA16816(d, a, b) \
    asm volatile("mma.sync.aligned.m16n8k16.row.col.f32.f16.f16.f32 " \
        "{%0,%1,%2,%3}, {%4,%5,%6,%7}, {%8,%9}, {%0,%1,%2,%3};" \
        : "+f"((d)[0]),"+f"((d)[1]),"+f"((d)[2]),"+f"((d)[3]) \
        : "r"((a)[0]),"r"((a)[1]),"r"((a)[2]),"r"((a)[3]), "r"((b)[0]),"r"((b)[1]))
#define CP_ASYNC16(dst, src) \
    asm volatile("cp.async.ca.shared.global [%0], [%1], 16;" :: "r"(dst), "l"(src) : "memory")
#define CP_COMMIT() asm volatile("cp.async.commit_group;" ::: "memory")
#define CP_WAIT(n)  asm volatile("cp.async.wait_group %0;" :: "n"(n) : "memory")

__device__ __forceinline__ unsigned cvtH2(float a, float b) {
    __half ha = __float2half(a), hb = __float2half(b);
    return (unsigned)__half_as_ushort(ha) | ((unsigned)__half_as_ushort(hb) << 16);
}
__device__ __forceinline__ unsigned swz(int row, int chunk) {
    return (unsigned)(row*256 + ((chunk ^ (row&7)) << 4));
}

// ---------------- K0a: weights -> fp16 ----------------
__global__ void k_cvtw(const float* __restrict__ W1, const float* __restrict__ W2)
{
    int i4 = (blockIdx.x*blockDim.x + threadIdx.x) * 4;
    const int n1 = EXPERTS*HDIM*FDIM;
    const int n2 = EXPERTS*ODIM*HDIM;
    if (i4 < n1){
        float4 v = *reinterpret_cast<const float4*>(W1 + i4);
        *reinterpret_cast<uint2*>(g_w1h + i4) = make_uint2(cvtH2(v.x,v.y), cvtH2(v.z,v.w));
    } else if (i4 - n1 < n2){
        int j4 = i4 - n1;
        float4 v = *reinterpret_cast<const float4*>(W2 + j4);
        *reinterpret_cast<uint2*>(g_w2h + j4) = make_uint2(cvtH2(v.x,v.y), cvtH2(v.z,v.w));
    }
}
// ---------------- K0b: features -> fp16 ----------------
__global__ void k_cvtf(const float* __restrict__ feat, int n)
{
    int i8 = (blockIdx.x*blockDim.x + threadIdx.x) * 8;
    if (i8 >= n) return;
    float4 a = *reinterpret_cast<const float4*>(feat + i8);
    float4 b = *reinterpret_cast<const float4*>(feat + i8 + 4);
    *reinterpret_cast<uint4*>(g_feat16 + i8) =
        make_uint4(cvtH2(a.x,a.y), cvtH2(a.z,a.w), cvtH2(b.x,b.y), cvtH2(b.z,b.w));
}

// ---------------- K1: gate scores (exact fp32) ----------------
__global__ void k_scores(const float* __restrict__ feat, const float* __restrict__ Wg,
                         const float* __restrict__ bg, int B)
{
    __shared__ float sW[EXPERTS*FDIM];
    __shared__ float sb[EXPERTS];
    for (int i = threadIdx.x; i < EXPERTS*FDIM; i += blockDim.x) sW[i] = Wg[i];
    if (threadIdx.x < EXPERTS) sb[threadIdx.x] = bg[threadIdx.x];
    __syncthreads();
    int b = blockIdx.x*blockDim.x + threadIdx.x;
    if (b >= B) return;
    const float4* row = reinterpret_cast<const float4*>(feat + (size_t)b*FDIM);
    float acc[EXPERTS];
#pragma unroll
    for (int e=0;e<EXPERTS;e++) acc[e] = sb[e];
#pragma unroll 4
    for (int j=0;j<FDIM/4;j++){
        float4 x = row[j];
#pragma unroll
        for (int e=0;e<EXPERTS;e++){
            float4 w = *reinterpret_cast<const float4*>(&sW[e*FDIM + j*4]);
            acc[e] += x.x*w.x + x.y*w.y + x.z*w.z + x.w*w.w;
        }
    }
#pragma unroll
    for (int e=0;e<EXPERTS;e++){
        unsigned u = __float_as_uint(acc[e]);
        u = (u & 0x80000000u) ? ~u : (u | 0x80000000u);
        g_keys[(size_t)e*B + b] = u;
        atomicAdd(&g_z.hist[e*65536 + (u>>16)], 1u);
    }
}

// ---------------- K2: 2-phase parallel descending scan ----------------
// which=0: hist, target=Mv, writes g_b16/g_rankInB
// which=1: hist2, target=g_rankInB[e], writes g_T/g_needEq
__global__ void k_scan(int which, int Mv)
{
    int e = blockIdx.y;
    int c = blockIdx.x;          // chunk 0..7 (c=0 = highest bins)
    int t = threadIdx.x;         // 1024
    const unsigned* h = (which ? g_z.hist2 : g_z.hist) + e*65536;

    __shared__ unsigned redbuf[32];
    __shared__ unsigned warpSum[32], warpPre[32];
    __shared__ int sLast;

    // phase 1: chunk total
    {
        int base = 65535 - c*8192 - t*8;
        const uint4* p = reinterpret_cast<const uint4*>(h + (base - 7));
        uint4 q0 = p[0], q1 = p[1];
        unsigned s = q0.x+q0.y+q0.z+q0.w+q1.x+q1.y+q1.z+q1.w;
        unsigned lane = t & 31, wd = t >> 5;
#pragma unroll
        for (int o=16;o>0;o>>=1) s += __shfl_down_sync(~0u, s, o);
        if (lane == 0) redbuf[wd] = s;
        __syncthreads();
        if (t == 0){
            unsigned total = 0;
            for (int k=0;k<32;k++) total += redbuf[k];
            g_csum[which][e][c] = total;
            __threadfence();
            sLast = (atomicAdd(&g_z.scnt[which][e], 1) == 7) ? 1 : 0;
        }
        __syncthreads();
        if (!sLast) return;
    }

    // phase 2 (one block per expert): find chunk, then exact bin
    unsigned target = which ? g_rankInB[e] : (unsigned)Mv;
    unsigned beforeC = 0; int cc = 0;
    {
        unsigned acc = 0; int found = 0;
        for (int k=0;k<8;k++){
            unsigned cs = g_csum[which][e][k];
            if (!found && acc + cs >= target){ cc = k; beforeC = acc; found = 1; }
            acc += cs;
        }
    }
    unsigned tloc = target - beforeC;

    int base2 = 65535 - cc*8192 - t*8;
    const uint4* p2 = reinterpret_cast<const uint4*>(h + (base2 - 7));
    uint4 q0 = p2[0], q1 = p2[1];
    unsigned b8[8] = { q1.w, q1.z, q1.y, q1.x, q0.w, q0.z, q0.y, q0.x }; // descending
    unsigned s = 0;
#pragma unroll
    for (int i=0;i<8;i++) s += b8[i];

    unsigned lane = t & 31, wd = t >> 5;
    unsigned inc = s;
#pragma unroll
    for (int o=1;o<32;o<<=1){ unsigned n = __shfl_up_sync(~0u, inc, o); if (lane >= o) inc += n; }
    if (lane == 31) warpSum[wd] = inc;
    __syncthreads();
    if (wd == 0){
        unsigned ws = warpSum[lane], winc = ws;
#pragma unroll
        for (int o=1;o<32;o<<=1){ unsigned n = __shfl_up_sync(~0u, winc, o); if (lane >= o) winc += n; }
        warpPre[lane] = winc - ws;
    }
    __syncthreads();
    unsigned before = warpPre[wd] + inc - s;
    if (before < tloc && tloc <= before + s){
        unsigned acc = before;
#pragma unroll
        for (int i=0;i<8;i++){
            unsigned cnt = b8[i];
            if (acc + cnt >= tloc){
                unsigned bin = (unsigned)(base2 - i);
                unsigned rank = tloc - acc;
                if (which){ g_T[e] = (g_b16[e] << 16) | bin; g_needEq[e] = rank; }
                else      { g_b16[e] = bin; g_rankInB[e] = rank; }
                break;
            }
            acc += cnt;
        }
    }
}

__global__ void k_hist2(int B){
    int e = blockIdx.y;
    int i = blockIdx.x*blockDim.x + threadIdx.x;
    if (i >= B) return;
    unsigned u = g_keys[(size_t)e*B + i];
    if ((u >> 16) == g_b16[e]) atomicAdd(&g_z.hist2[e*65536 + (u & 0xFFFFu)], 1u);
}

__global__ void k_select(int B){
    int e = blockIdx.y;
    int i = blockIdx.x*blockDim.x + threadIdx.x;
    int lane = threadIdx.x & 31;
    bool inb = (i < B);
    unsigned u = inb ? g_keys[(size_t)e*B + i] : 0u;
    unsigned t = g_T[e];
    bool gt = inb && (u > t);
    unsigned mask = __ballot_sync(~0u, gt);
    if (mask){
        int leader = __ffs(mask) - 1;
        int base = 0;
        if (lane == leader) base = atomicAdd(&g_z.idxCnt[e], __popc(mask));
        base = __shfl_sync(~0u, base, leader);
        if (gt){
            int p = base + __popc(mask & ((1u << lane) - 1u));
            g_idx[e*MMAX + p] = i;
            atomicOr(&g_z.selMask[i], 1u << e);
        }
    }
    if (inb && u == t){
        int p = atomicAdd(&g_z.eqCnt[e], 1);
        if (p < EQCAP) g_eqList[e*EQCAP + p] = i;
    }
}

__global__ void k_resolve(){
    int e = blockIdx.x;
    int n = g_z.eqCnt[e]; if (n > EQCAP) n = EQCAP;
    int need = (int)g_needEq[e];
    for (int j = threadIdx.x; j < n; j += blockDim.x){
        int v = g_eqList[e*EQCAP + j];
        int r = 0;
        for (int k=0;k<n;k++) r += (g_eqList[e*EQCAP + k] < v);
        if (r < need){
            int p = atomicAdd(&g_z.idxCnt[e], 1);
            g_idx[e*MMAX + p] = v;
            atomicOr(&g_z.selMask[v], 1u << e);
        }
    }
}

// ---------------- K8: 512-thread persistent-expert fp16 mma MLP, H double-buffered ----------------
#define HDR_IDXA  0
#define HDR_IDXB  512
#define HDR_B1    1024
#define HDR_B2    2048
#define POOL      2304
#define OFF_W1    (POOL + 0)        // 64KB
#define OFF_W2    (POOL + 65536)    // 32KB
#define OFF_XA    (POOL + 98304)    // 32KB
#define OFF_XB    (POOL + 131072)   // 32KB
#define OFF_H0    (POOL + 163840)   // 32KB (h=0)
#define OFF_H1    (POOL + 196608)   // 32KB (h=1)
#define SMEM_TOTAL (POOL + 229376)  // 231,680 bytes

__global__ __launch_bounds__(NTHR, 1)
void k_mlp(const float* __restrict__ b1, const float* __restrict__ b2,
           float* __restrict__ out, int Mv)
{
    extern __shared__ char smem[];
    uint32_t sbase = smem_u32(smem);
    int tid = threadIdx.x, lane = tid & 31, wid = tid >> 5;
    int e = blockIdx.y;
    int ntiles = (Mv + BM - 1) / BM;

    float* sB1 = (float*)(smem + HDR_B1);
    float* sB2 = (float*)(smem + HDR_B2);
    int* bufs[2] = { (int*)(smem + HDR_IDXA), (int*)(smem + HDR_IDXB) };
    uint32_t xoff[2] = { sbase + OFF_XA, sbase + OFF_XB };

    if (tid < HDIM) sB1[tid] = b1[e*HDIM + tid];
    if (tid < ODIM) sB2[tid] = b2[e*ODIM + tid];

    int t0 = blockIdx.x;
    if (t0 < ntiles && tid < BM){
        int slot = t0*BM + tid;
        bufs[0][tid] = (slot < Mv) ? g_idx[e*MMAX + slot] : 0;
    }
    __syncthreads();
    if (t0 < ntiles){
        const int* sI = bufs[0];
#pragma unroll
        for (int it=0; it<4; ++it){
            int s = it*NTHR + tid, row = s >> 4, cg = s & 15;
            const __half* src = g_feat16 + (size_t)sI[row]*FDIM + cg*8;
            CP_ASYNC16(xoff[0] + swz(row, cg), src);
        }
    }
    CP_COMMIT();

    // resident fp16 weights
#pragma unroll
    for (int it=0; it<8; ++it){
        int s = it*NTHR + tid, row = s >> 4, cg = s & 15;
        uint4 v = *reinterpret_cast<const uint4*>(g_w1h + (size_t)(e*HDIM + row)*FDIM + cg*8);
        *(uint4*)(smem + OFF_W1 + (row>>7)*32768 + swz(row&127, cg)) = v;
    }
#pragma unroll
    for (int it=0; it<4; ++it){
        int s = it*NTHR + tid, row = s >> 5, cgg = s & 31;
        uint4 v = *reinterpret_cast<const uint4*>(g_w2h + (size_t)(e*ODIM + row)*HDIM + cgg*8);
        *(uint4*)(smem + OFF_W2 + (cgg>>4)*16384 + swz(row, cgg&15)) = v;
    }

    int wm = wid & 3, wn = wid >> 2;   // 4m x 4n
    int m0 = wm * 32;
    int curbuf = 0;

    for (int t = t0; t < ntiles; t += NCTA){
        int* sIdxC = bufs[curbuf];
        int* sIdxN = bufs[curbuf ^ 1];
        uint32_t xc = xoff[curbuf], xn = xoff[curbuf ^ 1];

        __syncthreads();                      // [A] prev tile fully consumed (H, bufs, X)
        int tn = t + NCTA;
        if (tn < ntiles && tid < BM){
            int slot = tn*BM + tid;
            sIdxN[tid] = (slot < Mv) ? g_idx[e*MMAX + slot] : 0;
        }
        __syncthreads();                      // [B] sIdxN visible

        if (tn < ntiles){
#pragma unroll
            for (int it=0; it<4; ++it){
                int s = it*NTHR + tid, row = s >> 4, cg = s & 15;
                const __half* src = g_feat16 + (size_t)sIdxN[row]*FDIM + cg*8;
                CP_ASYNC16(xn + swz(row, cg), src);
            }
        }
        CP_COMMIT();
        CP_WAIT(1);
        __syncthreads();                      // [C] X[cur] visible

        float c2[2][2][4];
#pragma unroll
        for (int a=0;a<2;a++)
#pragma unroll
            for (int bb=0;bb<2;bb++)
#pragma unroll
                for (int i=0;i<4;i++) c2[a][bb][i] = 0.0f;

#pragma unroll 1
        for (int h=0; h<2; ++h){
            uint32_t hbase = sbase + OFF_H0 + h*32768;
            float c1[2][4][4];
#pragma unroll
            for (int a=0;a<2;a++)
#pragma unroll
                for (int bb=0;bb<4;bb++)
#pragma unroll
                    for (int i=0;i<4;i++) c1[a][bb][i] = 0.0f;

#pragma unroll 2
            for (int ks=0; ks<8; ++ks){
                uint32_t ah[2][4];
                int arow_l = lane & 15, achk = ks*2 + (lane >> 4);
#pragma unroll
                for (int mt=0; mt<2; ++mt){
                    int row = m0 + mt*16 + arow_l;
                    LDSM_X4(ah[mt][0],ah[mt][1],ah[mt][2],ah[mt][3], xc + swz(row, achk));
                }
                uint32_t bh[4][2];
                int brow_l = (lane & 7) + ((lane >> 4) << 3);
                int bchk = ks*2 + ((lane >> 3) & 1);
#pragma unroll
                for (int np=0; np<2; ++np){
                    int nrow = wn*32 + np*16 + brow_l;
                    uint32_t t0r,t1r,t2r,t3r;
                    LDSM_X4(t0r,t1r,t2r,t3r,
                            sbase + OFF_W1 + h*32768 + swz(nrow, bchk));
                    bh[np*2][0]=t0r; bh[np*2][1]=t1r; bh[np*2+1][0]=t2r; bh[np*2+1][1]=t3r;
                }
#pragma unroll
                for (int mt=0; mt<2; ++mt)
#pragma unroll
                    for (int nf=0; nf<4; ++nf)
                        MMA16816(c1[mt][nf], ah[mt], bh[nf]);
            }

            // epilogue1: +b1, relu -> H[h]
#pragma unroll
            for (int mt=0; mt<2; ++mt)
#pragma unroll
                for (int nf=0; nf<4; ++nf)
#pragma unroll
                    for (int i2=0; i2<2; ++i2){
                        int row = m0 + mt*16 + (lane>>2) + 8*i2;
                        int col = wn*32 + nf*8 + (lane&3)*2;
                        float v0 = fmaxf(c1[mt][nf][i2*2+0] + sB1[h*128 + col],     0.0f);
                        float v1 = fmaxf(c1[mt][nf][i2*2+1] + sB1[h*128 + col + 1], 0.0f);
                        *(uint32_t*)((char*)smem + (hbase - sbase) + swz(row, col>>3) + (col&7)*2) = cvtH2(v0, v1);
                    }
            __syncthreads();                  // [D/E] H[h] ready (no tail sync: next write goes to other H buffer)

#pragma unroll 2
            for (int ks=0; ks<8; ++ks){
                uint32_t ah[2][4];
                int arow_l = lane & 15, achk = ks*2 + (lane >> 4);
#pragma unroll
                for (int mt=0; mt<2; ++mt){
                    int row = m0 + mt*16 + arow_l;
                    LDSM_X4(ah[mt][0],ah[mt][1],ah[mt][2],ah[mt][3], hbase + swz(row, achk));
                }
                uint32_t bh[2][2];
                {
                    int nrow = wn*16 + (lane & 7) + ((lane >> 4) << 3);
                    int bchk = ks*2 + ((lane >> 3) & 1);
                    uint32_t t0r,t1r,t2r,t3r;
                    LDSM_X4(t0r,t1r,t2r,t3r,
                            sbase + OFF_W2 + h*16384 + swz(nrow, bchk));
                    bh[0][0]=t0r; bh[0][1]=t1r; bh[1][0]=t2r; bh[1][1]=t3r;
                }
#pragma unroll
                for (int mt=0; mt<2; ++mt)
#pragma unroll
                    for (int nf=0; nf<2; ++nf)
                        MMA16816(c2[mt][nf], ah[mt], bh[nf]);
            }
        }

        // ---- scatter: w = 1/popc(selMask); m==1 -> STG.64, m>1 -> atomicAdd ----
#pragma unroll
        for (int mt=0; mt<2; ++mt)
#pragma unroll
            for (int nf=0; nf<2; ++nf)
#pragma unroll
                for (int r2=0; r2<2; ++r2){
                    int row = m0 + mt*16 + (lane>>2) + 8*r2;
                    int col = wn*16 + nf*8 + (lane&3)*2;
                    int tk  = sIdxC[row];
                    int cm  = ((t*BM + row) < Mv) ? __popc(g_z.selMask[tk]) : 0;
                    float* dst = &out[(size_t)tk*ODIM + col];
                    if (cm == 1){
                        *reinterpret_cast<float2*>(dst) =
                            make_float2(c2[mt][nf][r2*2+0] + sB2[col],
                                        c2[mt][nf][r2*2+1] + sB2[col+1]);
                    } else if (cm > 1){
                        float w = 1.0f / (float)cm;
                        atomicAdd(dst,   (c2[mt][nf][r2*2+0] + sB2[col])   * w);
                        atomicAdd(dst+1, (c2[mt][nf][r2*2+1] + sB2[col+1]) * w);
                    }
                }

        curbuf ^= 1;
    }
}

// ---------------- launch ----------------
extern "C" void kernel_launch(void* const* d_in, const int* in_sizes, int n_in,
                              void* d_out, int out_size)
{
    const float* feat = (const float*)d_in[0];
    const float* Wg   = (const float*)d_in[1];
    const float* bg   = (const float*)d_in[2];
    const float* W1   = (const float*)d_in[3];
    const float* b1   = (const float*)d_in[4];
    const float* W2   = (const float*)d_in[5];
    const float* b2   = (const float*)d_in[6];
    float* out = (float*)d_out;

    int B = in_sizes[0] / FDIM;
    int Mv = (B + EXPERTS - 1) / EXPERTS;
    if (Mv < 1) Mv = 1;
    if (Mv > B) Mv = B;

    void* p_z;
    cudaGetSymbolAddress(&p_z, g_z);
    cudaMemsetAsync(p_z, 0, sizeof(ZeroBlk), 0);
    cudaMemsetAsync(d_out, 0, (size_t)out_size*sizeof(float), 0);

    int tb = 256;
    int gb = (B + tb - 1)/tb;
    k_cvtw<<<768, 256>>>(W1, W2);
    k_cvtf<<<(B*FDIM/8 + 255)/256, 256>>>(feat, B*FDIM);
    k_scores<<<gb, tb>>>(feat, Wg, bg, B);
    k_scan<<<dim3(8, EXPERTS), 1024>>>(0, Mv);
    k_hist2<<<dim3(gb, EXPERTS), tb>>>(B);
    k_scan<<<dim3(8, EXPERTS), 1024>>>(1, Mv);
    k_select<<<dim3(gb, EXPERTS), tb>>>(B);
    k_resolve<<<EXPERTS, 256>>>();

    cudaFuncSetAttribute(k_mlp, cudaFuncAttributeMaxDynamicSharedMemorySize, SMEM_TOTAL);
    k_mlp<<<dim3(NCTA, EXPERTS), NTHR, SMEM_TOTAL>>>(b1, b2, out, Mv);
}

// round 17
// speedup vs baseline: 1.0549x; 1.0549x over previous
#include <cuda_runtime.h>
#include <cuda_fp16.h>
#include <cstdint>

#define EXPERTS 16
#define FDIM 128
#define HDIM 256
#define ODIM 64
#define BMAX 262144
#define MMAX (BMAX/EXPERTS)
#define EQCAP 8192
#define BM 128
#define GRIDX 148
#define NTHR 512

// ---------------- scratch ----------------
struct ZeroBlk {
    unsigned hist[EXPERTS * 65536];
    unsigned hist2[EXPERTS * 65536];
    unsigned selMask[BMAX];
    int      eqCnt[EXPERTS];
    int      idxCnt[EXPERTS];
    int      scnt[2][EXPERTS];
};
__device__ ZeroBlk  g_z;
__device__ unsigned g_csum[2][EXPERTS][8];
__device__ unsigned g_keys[(size_t)EXPERTS * BMAX];
__device__ unsigned g_b16[EXPERTS];
__device__ unsigned g_rankInB[EXPERTS];
__device__ unsigned g_T[EXPERTS];
__device__ unsigned g_needEq[EXPERTS];
__device__ int      g_eqList[EXPERTS * EQCAP];
__device__ int      g_idx[EXPERTS * MMAX];
__device__ float    g_invm[BMAX];
__device__ __half   g_w1h[(size_t)EXPERTS * HDIM * FDIM];
__device__ __half   g_w2h[(size_t)EXPERTS * ODIM * HDIM];
__device__ __half   g_feat16[(size_t)BMAX * FDIM];

// ---------------- helpers ----------------
__device__ __forceinline__ uint32_t smem_u32(const void* p) {
    uint32_t a;
    asm("{ .reg .u64 t; cvta.to.shared.u64 t, %1; cvt.u32.u64 %0, t; }" : "=r"(a) : "l"(p));
    return a;
}
#define LDSM_X4(r0,r1,r2,r3, addr) \
    asm volatile("ldmatrix.sync.aligned.m8n8.x4.shared.b16 {%0,%1,%2,%3}, [%4];" \
        : "=r"(r0),"=r"(r1),"=r"(r2),"=r"(r3) : "r"(addr))
#define MMA16816(d, a, b) \
    asm volatile("mma.sync.aligned.m16n8k16.row.col.f32.f16.f16.f32 " \
        "{%0,%1,%2,%3}, {%4,%5,%6,%7}, {%8,%9}, {%0,%1,%2,%3};" \
        : "+f"((d)[0]),"+f"((d)[1]),"+f"((d)[2]),"+f"((d)[3]) \
        : "r"((a)[0]),"r"((a)[1]),"r"((a)[2]),"r"((a)[3]), "r"((b)[0]),"r"((b)[1]))
#define CP_ASYNC16(dst, src) \
    asm volatile("cp.async.ca.shared.global [%0], [%1], 16;" :: "r"(dst), "l"(src) : "memory")
#define CP_COMMIT() asm volatile("cp.async.commit_group;" ::: "memory")
#define CP_WAIT(n)  asm volatile("cp.async.wait_group %0;" :: "n"(n) : "memory")

__device__ __forceinline__ unsigned cvtH2(float a, float b) {
    __half ha = __float2half(a), hb = __float2half(b);
    return (unsigned)__half_as_ushort(ha) | ((unsigned)__half_as_ushort(hb) << 16);
}
__device__ __forceinline__ unsigned swz(int row, int chunk) {
    return (unsigned)(row*256 + ((chunk ^ (row&7)) << 4));
}

// ---------------- K0: weights -> fp16 ----------------
__global__ void k_cvtw(const float* __restrict__ W1, const float* __restrict__ W2)
{
    int i4 = (blockIdx.x*blockDim.x + threadIdx.x) * 4;
    const int n1 = EXPERTS*HDIM*FDIM;
    const int n2 = EXPERTS*ODIM*HDIM;
    if (i4 < n1){
        float4 v = *reinterpret_cast<const float4*>(W1 + i4);
        *reinterpret_cast<uint2*>(g_w1h + i4) = make_uint2(cvtH2(v.x,v.y), cvtH2(v.z,v.w));
    } else if (i4 - n1 < n2){
        int j4 = i4 - n1;
        float4 v = *reinterpret_cast<const float4*>(W2 + j4);
        *reinterpret_cast<uint2*>(g_w2h + j4) = make_uint2(cvtH2(v.x,v.y), cvtH2(v.z,v.w));
    }
}

// ---------------- K1: gate scores (exact fp32) + fused feat->fp16 ----------------
__global__ void k_scores(const float* __restrict__ feat, const float* __restrict__ Wg,
                         const float* __restrict__ bg, int B)
{
    __shared__ float sW[EXPERTS*FDIM];
    __shared__ float sb[EXPERTS];
    for (int i = threadIdx.x; i < EXPERTS*FDIM; i += blockDim.x) sW[i] = Wg[i];
    if (threadIdx.x < EXPERTS) sb[threadIdx.x] = bg[threadIdx.x];
    __syncthreads();
    int b = blockIdx.x*blockDim.x + threadIdx.x;
    if (b < B){
        const float4* row = reinterpret_cast<const float4*>(feat + (size_t)b*FDIM);
        float acc[EXPERTS];
#pragma unroll
        for (int e=0;e<EXPERTS;e++) acc[e] = sb[e];
#pragma unroll 4
        for (int j=0;j<FDIM/4;j++){
            float4 x = row[j];
#pragma unroll
            for (int e=0;e<EXPERTS;e++){
                float4 w = *reinterpret_cast<const float4*>(&sW[e*FDIM + j*4]);
                acc[e] += x.x*w.x + x.y*w.y + x.z*w.z + x.w*w.w;
            }
        }
#pragma unroll
        for (int e=0;e<EXPERTS;e++){
            unsigned u = __float_as_uint(acc[e]);
            u = (u & 0x80000000u) ? ~u : (u | 0x80000000u);
            g_keys[(size_t)e*B + b] = u;
            atomicAdd(&g_z.hist[e*65536 + (u>>16)], 1u);
        }
    }
    // fused conversion of this block's slab (L2-hot re-read, coalesced write)
    int rbase = blockIdx.x * blockDim.x;
#pragma unroll
    for (int it=0; it<16; ++it){
        int s = it*256 + threadIdx.x;
        int row = rbase + (s >> 4);
        int seg = s & 15;
        if (row < B){
            const float* src = feat + (size_t)row*FDIM + seg*8;
            float4 a = *reinterpret_cast<const float4*>(src);
            float4 c = *reinterpret_cast<const float4*>(src + 4);
            *reinterpret_cast<uint4*>(g_feat16 + (size_t)row*FDIM + seg*8) =
                make_uint4(cvtH2(a.x,a.y), cvtH2(a.z,a.w), cvtH2(c.x,c.y), cvtH2(c.z,c.w));
        }
    }
}

// ---------------- K2: 2-phase parallel descending scan ----------------
__global__ void k_scan(int which, int Mv)
{
    int e = blockIdx.y;
    int c = blockIdx.x;
    int t = threadIdx.x;
    const unsigned* h = (which ? g_z.hist2 : g_z.hist) + e*65536;

    __shared__ unsigned redbuf[32];
    __shared__ unsigned warpSum[32], warpPre[32];
    __shared__ int sLast;

    {
        int base = 65535 - c*8192 - t*8;
        const uint4* p = reinterpret_cast<const uint4*>(h + (base - 7));
        uint4 q0 = p[0], q1 = p[1];
        unsigned s = q0.x+q0.y+q0.z+q0.w+q1.x+q1.y+q1.z+q1.w;
        unsigned lane = t & 31, wd = t >> 5;
#pragma unroll
        for (int o=16;o>0;o>>=1) s += __shfl_down_sync(~0u, s, o);
        if (lane == 0) redbuf[wd] = s;
        __syncthreads();
        if (t == 0){
            unsigned total = 0;
            for (int k=0;k<32;k++) total += redbuf[k];
            g_csum[which][e][c] = total;
            __threadfence();
            sLast = (atomicAdd(&g_z.scnt[which][e], 1) == 7) ? 1 : 0;
        }
        __syncthreads();
        if (!sLast) return;
    }

    unsigned target = which ? g_rankInB[e] : (unsigned)Mv;
    unsigned beforeC = 0; int cc = 0;
    {
        unsigned acc = 0; int found = 0;
        for (int k=0;k<8;k++){
            unsigned cs = g_csum[which][e][k];
            if (!found && acc + cs >= target){ cc = k; beforeC = acc; found = 1; }
            acc += cs;
        }
    }
    unsigned tloc = target - beforeC;

    int base2 = 65535 - cc*8192 - t*8;
    const uint4* p2 = reinterpret_cast<const uint4*>(h + (base2 - 7));
    uint4 q0 = p2[0], q1 = p2[1];
    unsigned b8[8] = { q1.w, q1.z, q1.y, q1.x, q0.w, q0.z, q0.y, q0.x };
    unsigned s = 0;
#pragma unroll
    for (int i=0;i<8;i++) s += b8[i];

    unsigned lane = t & 31, wd = t >> 5;
    unsigned inc = s;
#pragma unroll
    for (int o=1;o<32;o<<=1){ unsigned n = __shfl_up_sync(~0u, inc, o); if (lane >= o) inc += n; }
    if (lane == 31) warpSum[wd] = inc;
    __syncthreads();
    if (wd == 0){
        unsigned ws = warpSum[lane], winc = ws;
#pragma unroll
        for (int o=1;o<32;o<<=1){ unsigned n = __shfl_up_sync(~0u, winc, o); if (lane >= o) winc += n; }
        warpPre[lane] = winc - ws;
    }
    __syncthreads();
    unsigned before = warpPre[wd] + inc - s;
    if (before < tloc && tloc <= before + s){
        unsigned acc = before;
#pragma unroll
        for (int i=0;i<8;i++){
            unsigned cnt = b8[i];
            if (acc + cnt >= tloc){
                unsigned bin = (unsigned)(base2 - i);
                unsigned rank = tloc - acc;
                if (which){ g_T[e] = (g_b16[e] << 16) | bin; g_needEq[e] = rank; }
                else      { g_b16[e] = bin; g_rankInB[e] = rank; }
                break;
            }
            acc += cnt;
        }
    }
}

__global__ void k_hist2(int B){
    int e = blockIdx.y;
    int i = blockIdx.x*blockDim.x + threadIdx.x;
    if (i >= B) return;
    unsigned u = g_keys[(size_t)e*B + i];
    if ((u >> 16) == g_b16[e]) atomicAdd(&g_z.hist2[e*65536 + (u & 0xFFFFu)], 1u);
}

__global__ void k_select(int B){
    int e = blockIdx.y;
    int i = blockIdx.x*blockDim.x + threadIdx.x;
    int lane = threadIdx.x & 31;
    bool inb = (i < B);
    unsigned u = inb ? g_keys[(size_t)e*B + i] : 0u;
    unsigned t = g_T[e];
    bool gt = inb && (u > t);
    unsigned mask = __ballot_sync(~0u, gt);
    if (mask){
        int leader = __ffs(mask) - 1;
        int base = 0;
        if (lane == leader) base = atomicAdd(&g_z.idxCnt[e], __popc(mask));
        base = __shfl_sync(~0u, base, leader);
        if (gt){
            int p = base + __popc(mask & ((1u << lane) - 1u));
            g_idx[e*MMAX + p] = i;
            atomicOr(&g_z.selMask[i], 1u << e);
        }
    }
    if (inb && u == t){
        int p = atomicAdd(&g_z.eqCnt[e], 1);
        if (p < EQCAP) g_eqList[e*EQCAP + p] = i;
    }
}

__global__ void k_resolve(){
    int e = blockIdx.x;
    int n = g_z.eqCnt[e]; if (n > EQCAP) n = EQCAP;
    int need = (int)g_needEq[e];
    for (int j = threadIdx.x; j < n; j += blockDim.x){
        int v = g_eqList[e*EQCAP + j];
        int r = 0;
        for (int k=0;k<n;k++) r += (g_eqList[e*EQCAP + k] < v);
        if (r < need){
            int p = atomicAdd(&g_z.idxCnt[e], 1);
            g_idx[e*MMAX + p] = v;
            atomicOr(&g_z.selMask[v], 1u << e);
        }
    }
}

__global__ void k_invm(int B){
    int i = blockIdx.x*blockDim.x + threadIdx.x;
    if (i>=B) return;
    int c = __popc(g_z.selMask[i]);
    g_invm[i] = 1.0f / (float)(c > 0 ? c : 1);
}

// ---------------- K8: flat-grid persistent fp16 mma MLP (R15 compute core) ----------------
#define HDR_IDXA  0
#define HDR_IDXB  512
#define HDR_B1    1024
#define HDR_B2    2048
#define POOL      2304
#define OFF_W1    (POOL + 0)        // 64KB
#define OFF_W2    (POOL + 65536)    // 32KB
#define OFF_XA    (POOL + 98304)    // 32KB
#define OFF_XB    (POOL + 131072)   // 32KB
#define OFF_H     (POOL + 163840)   // 32KB
#define SMEM_TOTAL (POOL + 196608)  // 198,912 bytes

__global__ __launch_bounds__(NTHR, 1)
void k_mlp(const float* __restrict__ b1, const float* __restrict__ b2,
           float* __restrict__ out, int Mv)
{
    extern __shared__ char smem[];
    uint32_t sbase = smem_u32(smem);
    int tid = threadIdx.x, lane = tid & 31, wid = tid >> 5;
    int ntiles_e = (Mv + BM - 1) / BM;
    int total = ntiles_e * EXPERTS;

    int cta = blockIdx.x;
    int tstart = (int)(((long long)cta * total) / GRIDX);
    int tend   = (int)(((long long)(cta+1) * total) / GRIDX);
    if (tstart >= tend) return;

    float* sB1 = (float*)(smem + HDR_B1);
    float* sB2 = (float*)(smem + HDR_B2);
    int* bufs[2] = { (int*)(smem + HDR_IDXA), (int*)(smem + HDR_IDXB) };
    uint32_t xoff[2] = { sbase + OFF_XA, sbase + OFF_XB };

    // prologue: indices + gather for first tile
    {
        int e0 = tstart / ntiles_e, l0 = tstart % ntiles_e;
        if (tid < BM){
            int slot = l0*BM + tid;
            bufs[0][tid] = (slot < Mv) ? g_idx[e0*MMAX + slot] : 0;
        }
        __syncthreads();
        const int* sI = bufs[0];
#pragma unroll
        for (int it=0; it<4; ++it){
            int s = it*NTHR + tid, row = s >> 4, cg = s & 15;
            const __half* src = g_feat16 + (size_t)sI[row]*FDIM + cg*8;
            CP_ASYNC16(xoff[0] + swz(row, cg), src);
        }
    }
    CP_COMMIT();

    int wm = wid & 3, wn = wid >> 2;   // 4m x 4n
    int m0 = wm * 32;
    int curbuf = 0;
    int ecur = -1;

    for (int t = tstart; t < tend; ++t){
        int e  = t / ntiles_e;
        int lt = t % ntiles_e;
        int* sIdxC = bufs[curbuf];
        int* sIdxN = bufs[curbuf ^ 1];
        uint32_t xc = xoff[curbuf], xn = xoff[curbuf ^ 1];

        __syncthreads();                      // [A] prev tile fully consumed

        if (e != ecur){
            // load this expert's weights + biases (at most 2x per CTA)
#pragma unroll
            for (int it=0; it<8; ++it){
                int s = it*NTHR + tid, row = s >> 4, cg = s & 15;
                uint4 v = *reinterpret_cast<const uint4*>(g_w1h + (size_t)(e*HDIM + row)*FDIM + cg*8);
                *(uint4*)(smem + OFF_W1 + (row>>7)*32768 + swz(row&127, cg)) = v;
            }
#pragma unroll
            for (int it=0; it<4; ++it){
                int s = it*NTHR + tid, row = s >> 5, cgg = s & 31;
                uint4 v = *reinterpret_cast<const uint4*>(g_w2h + (size_t)(e*ODIM + row)*HDIM + cgg*8);
                *(uint4*)(smem + OFF_W2 + (cgg>>4)*16384 + swz(row, cgg&15)) = v;
            }
            if (tid < HDIM) sB1[tid] = b1[e*HDIM + tid];
            if (tid < ODIM) sB2[tid] = b2[e*ODIM + tid];
            ecur = e;
        }

        int tn = t + 1;
        if (tn < tend && tid < BM){
            int en = tn / ntiles_e, ln = tn % ntiles_e;
            int slot = ln*BM + tid;
            sIdxN[tid] = (slot < Mv) ? g_idx[en*MMAX + slot] : 0;
        }
        __syncthreads();                      // [B] sIdxN + weights visible

        if (tn < tend){
#pragma unroll
            for (int it=0; it<4; ++it){
                int s = it*NTHR + tid, row = s >> 4, cg = s & 15;
                const __half* src = g_feat16 + (size_t)sIdxN[row]*FDIM + cg*8;
                CP_ASYNC16(xn + swz(row, cg), src);
            }
        }
        CP_COMMIT();
        CP_WAIT(1);
        __syncthreads();                      // [C] X[cur] visible

        float c2[2][2][4];
#pragma unroll
        for (int a=0;a<2;a++)
#pragma unroll
            for (int bb=0;bb<2;bb++)
#pragma unroll
                for (int i=0;i<4;i++) c2[a][bb][i] = 0.0f;

#pragma unroll 1
        for (int h=0; h<2; ++h){
            float c1[2][4][4];
#pragma unroll
            for (int a=0;a<2;a++)
#pragma unroll
                for (int bb=0;bb<4;bb++)
#pragma unroll
                    for (int i=0;i<4;i++) c1[a][bb][i] = 0.0f;

#pragma unroll 2
            for (int ks=0; ks<8; ++ks){
                uint32_t ah[2][4];
                int arow_l = lane & 15, achk = ks*2 + (lane >> 4);
#pragma unroll
                for (int mt=0; mt<2; ++mt){
                    int row = m0 + mt*16 + arow_l;
                    LDSM_X4(ah[mt][0],ah[mt][1],ah[mt][2],ah[mt][3], xc + swz(row, achk));
                }
                uint32_t bh[4][2];
                int brow_l = (lane & 7) + ((lane >> 4) << 3);
                int bchk = ks*2 + ((lane >> 3) & 1);
#pragma unroll
                for (int np=0; np<2; ++np){
                    int nrow = wn*32 + np*16 + brow_l;
                    uint32_t t0r,t1r,t2r,t3r;
                    LDSM_X4(t0r,t1r,t2r,t3r,
                            sbase + OFF_W1 + h*32768 + swz(nrow, bchk));
                    bh[np*2][0]=t0r; bh[np*2][1]=t1r; bh[np*2+1][0]=t2r; bh[np*2+1][1]=t3r;
                }
#pragma unroll
                for (int mt=0; mt<2; ++mt)
#pragma unroll
                    for (int nf=0; nf<4; ++nf)
                        MMA16816(c1[mt][nf], ah[mt], bh[nf]);
            }

            // epilogue1: +b1, relu -> H fp16
#pragma unroll
            for (int mt=0; mt<2; ++mt)
#pragma unroll
                for (int nf=0; nf<4; ++nf)
#pragma unroll
                    for (int i2=0; i2<2; ++i2){
                        int row = m0 + mt*16 + (lane>>2) + 8*i2;
                        int col = wn*32 + nf*8 + (lane&3)*2;
                        float v0 = fmaxf(c1[mt][nf][i2*2+0] + sB1[h*128 + col],     0.0f);
                        float v1 = fmaxf(c1[mt][nf][i2*2+1] + sB1[h*128 + col + 1], 0.0f);
                        *(uint32_t*)(smem + OFF_H + swz(row, col>>3) + (col&7)*2) = cvtH2(v0, v1);
                    }
            __syncthreads();                  // [D] H ready

#pragma unroll 2
            for (int ks=0; ks<8; ++ks){
                uint32_t ah[2][4];
                int arow_l = lane & 15, achk = ks*2 + (lane >> 4);
#pragma unroll
                for (int mt=0; mt<2; ++mt){
                    int row = m0 + mt*16 + arow_l;
                    LDSM_X4(ah[mt][0],ah[mt][1],ah[mt][2],ah[mt][3],
                            sbase + OFF_H + swz(row, achk));
                }
                uint32_t bh[2][2];
                {
                    int nrow = wn*16 + (lane & 7) + ((lane >> 4) << 3);
                    int bchk = ks*2 + ((lane >> 3) & 1);
                    uint32_t t0r,t1r,t2r,t3r;
                    LDSM_X4(t0r,t1r,t2r,t3r,
                            sbase + OFF_W2 + h*16384 + swz(nrow, bchk));
                    bh[0][0]=t0r; bh[0][1]=t1r; bh[1][0]=t2r; bh[1][1]=t3r;
                }
#pragma unroll
                for (int mt=0; mt<2; ++mt)
#pragma unroll
                    for (int nf=0; nf<2; ++nf)
                        MMA16816(c2[mt][nf], ah[mt], bh[nf]);
            }
            __syncthreads();                  // [E] H free for next half
        }

        // ---- scatter: m==1 -> direct STG.64; m>1 -> atomicAdd ----
#pragma unroll
        for (int mt=0; mt<2; ++mt)
#pragma unroll
            for (int nf=0; nf<2; ++nf)
#pragma unroll
                for (int r2=0; r2<2; ++r2){
                    int row = m0 + mt*16 + (lane>>2) + 8*r2;
                    int col = wn*16 + nf*8 + (lane&3)*2;
                    int tk  = sIdxC[row];
                    float w = ((lt*BM + row) < Mv) ? g_invm[tk] : 0.0f;
                    float y0 = (c2[mt][nf][r2*2+0] + sB2[col])   * w;
                    float y1 = (c2[mt][nf][r2*2+1] + sB2[col+1]) * w;
                    float* dst = &out[(size_t)tk*ODIM + col];
                    if (w == 1.0f){
                        *reinterpret_cast<float2*>(dst) = make_float2(y0, y1);
                    } else if (w > 0.0f){
                        atomicAdd(dst,   y0);
                        atomicAdd(dst+1, y1);
                    }
                }

        curbuf ^= 1;
    }
}

// ---------------- launch ----------------
extern "C" void kernel_launch(void* const* d_in, const int* in_sizes, int n_in,
                              void* d_out, int out_size)
{
    const float* feat = (const float*)d_in[0];
    const float* Wg   = (const float*)d_in[1];
    const float* bg   = (const float*)d_in[2];
    const float* W1   = (const float*)d_in[3];
    const float* b1   = (const float*)d_in[4];
    const float* W2   = (const float*)d_in[5];
    const float* b2   = (const float*)d_in[6];
    float* out = (float*)d_out;

    int B = in_sizes[0] / FDIM;
    int Mv = (B + EXPERTS - 1) / EXPERTS;
    if (Mv < 1) Mv = 1;
    if (Mv > B) Mv = B;

    void* p_z;
    cudaGetSymbolAddress(&p_z, g_z);
    cudaMemsetAsync(p_z, 0, sizeof(ZeroBlk), 0);
    cudaMemsetAsync(d_out, 0, (size_t)out_size*sizeof(float), 0);

    int tb = 256;
    int gb = (B + tb - 1)/tb;
    k_cvtw<<<768, 256>>>(W1, W2);
    k_scores<<<gb, tb>>>(feat, Wg, bg, B);
    k_scan<<<dim3(8, EXPERTS), 1024>>>(0, Mv);
    k_hist2<<<dim3(gb, EXPERTS), tb>>>(B);
    k_scan<<<dim3(8, EXPERTS), 1024>>>(1, Mv);
    k_select<<<dim3(gb, EXPERTS), tb>>>(B);
    k_resolve<<<EXPERTS, 256>>>();
    k_invm<<<gb, tb>>>(B);

    cudaFuncSetAttribute(k_mlp, cudaFuncAttributeMaxDynamicSharedMemorySize, SMEM_TOTAL);
    k_mlp<<<GRIDX, NTHR, SMEM_TOTAL>>>(b1, b2, out, Mv);
}